// round 3
// baseline (speedup 1.0000x reference)
#include <cuda_runtime.h>
#include <cuda_fp16.h>
#include <cstdint>

// ============================================================
// LSTM cell on GB300 (sm_103 PTX target — no tcgen05 available,
// so use legacy mma.sync HMMA path).
//   gates = [x|h] @ [Wf|Wi|Wc|Wo] + b  ->  GEMM M=4096, N=8192, K=4096
//   then elementwise LSTM epilogue.
// K1: pack z=[x|h] -> fp16 (K contiguous)
// K2: transpose W -> Wt[n][k] fp16, n = gate*2048 + u
// K3: GEMM 128x128x32 tiles, mma.sync.m16n8k16, 3-stage cp.async
//     -> fp32 gates scratch
// K4: elementwise epilogue -> new_h, new_c
// ============================================================

#define BROWS 4096
#define DIN   2048
#define UNITS 2048
#define KTOT  4096
#define NTOT  8192

#define BM 128
#define BN 128
#define BK 32
#define NITER (KTOT / BK)    // 128
#define STAGES 3

// SMEM: padded rows, 32 halfs data + 8 halfs pad = 80 bytes/row
#define ROWB 80
#define ATILE (BM * ROWB)            // 10240 bytes per stage
#define BTILE (BN * ROWB)            // 10240
#define SM_BOFF (STAGES * ATILE)     // 30720
#define SMEM_TOTAL (STAGES * (ATILE + BTILE))   // 61440

// -------- device scratch --------
__device__ __half g_Z [(size_t)BROWS * KTOT];    // 32 MB
__device__ __half g_Wt[(size_t)NTOT  * KTOT];    // 64 MB
__device__ float  g_G [(size_t)BROWS * NTOT];    // 128 MB fp32 gates

// -------- helpers --------
__device__ __forceinline__ uint32_t smem_u32(const void* p) {
    uint32_t a;
    asm("{ .reg .u64 t; cvta.to.shared.u64 t, %1; cvt.u32.u64 %0, t; }" : "=r"(a) : "l"(p));
    return a;
}
__device__ __forceinline__ void cp16(uint32_t dst, const void* src) {
    asm volatile("cp.async.cg.shared.global [%0], [%1], 16;" :: "r"(dst), "l"(src));
}
#define CP_COMMIT() asm volatile("cp.async.commit_group;" ::: "memory")
#define CP_WAIT(n)  asm volatile("cp.async.wait_group %0;" :: "n"(n) : "memory")

__device__ __forceinline__ float sigf(float x)      { return 1.f / (1.f + __expf(-x)); }
__device__ __forceinline__ float tanhfast(float x)  { return 1.f - 2.f / (__expf(2.f * x) + 1.f); }

// ============================================================
// K1: pack z = [x | h] -> fp16, K contiguous
// ============================================================
__global__ void pack_z_kernel(const float* __restrict__ x, const float* __restrict__ h) {
    int i = blockIdx.x * blockDim.x + threadIdx.x;      // over 4096*4096
    int row = i >> 12;
    int col = i & 4095;
    float v = (col < DIN) ? x[(size_t)row * DIN + col]
                          : h[(size_t)row * UNITS + (col - DIN)];
    g_Z[i] = __float2half_rn(v);
}

// ============================================================
// K2: Wt[n][k] = W_gate[k][u] fp16, n = gate*UNITS + u (K contiguous)
// grid (KTOT/64, UNITS/32, 4), block (32, 8)
// ============================================================
__global__ void transpose_w_kernel(const float* __restrict__ Wf, const float* __restrict__ Wi,
                                   const float* __restrict__ Wc, const float* __restrict__ Wo) {
    __shared__ float t[64][33];
    int k0 = blockIdx.x * 64;
    int u0 = blockIdx.y * 32;
    int gz = blockIdx.z;
    const float* W = (gz == 0) ? Wf : (gz == 1) ? Wi : (gz == 2) ? Wc : Wo;
    int tx = threadIdx.x, ty = threadIdx.y;

    #pragma unroll
    for (int r = ty; r < 64; r += 8)
        t[r][tx] = W[(size_t)(k0 + r) * UNITS + u0 + tx];
    __syncthreads();

    #pragma unroll
    for (int uu = ty; uu < 32; uu += 8) {
        int n = gz * UNITS + u0 + uu;
        __half2 v;
        v.x = __float2half_rn(t[2 * tx][uu]);
        v.y = __float2half_rn(t[2 * tx + 1][uu]);
        *reinterpret_cast<__half2*>(&g_Wt[(size_t)n * KTOT + k0 + 2 * tx]) = v;
    }
}

// ============================================================
// K3: GEMM, mma.sync HMMA path
// ============================================================
__device__ __forceinline__ void load_stage(uint32_t sb, int tid, int m0, int n0,
                                           int s, int buf) {
    const int k0 = s * BK;
    #pragma unroll
    for (int j = 0; j < 2; ++j) {               // A: 512 chunks of 16B
        int c   = tid + j * 256;
        int row = c >> 2, kc = c & 3;
        uint32_t d = sb + buf * ATILE + row * ROWB + kc * 16;
        cp16(d, &g_Z[(size_t)(m0 + row) * KTOT + k0 + kc * 8]);
    }
    #pragma unroll
    for (int j = 0; j < 2; ++j) {               // B: 512 chunks of 16B
        int c   = tid + j * 256;
        int row = c >> 2, kc = c & 3;
        uint32_t d = sb + SM_BOFF + buf * BTILE + row * ROWB + kc * 16;
        cp16(d, &g_Wt[(size_t)(n0 + row) * KTOT + k0 + kc * 8]);
    }
}

__device__ __forceinline__ void compute_stage(uint32_t aBase, uint32_t bBase,
                                              int warp_m, int warp_n, int lane,
                                              float acc[4][4][4]) {
    #pragma unroll
    for (int ks = 0; ks < 2; ++ks) {            // two k16 steps per BK=32
        uint32_t a[4][4];
        uint32_t b[4][2];
        #pragma unroll
        for (int mi = 0; mi < 4; ++mi) {
            uint32_t addr = aBase + (uint32_t)(warp_m * 64 + mi * 16 + (lane & 15)) * ROWB
                          + ks * 32 + ((lane >> 4) << 4);
            asm volatile("ldmatrix.sync.aligned.m8n8.x4.shared.b16 {%0,%1,%2,%3}, [%4];"
                : "=r"(a[mi][0]), "=r"(a[mi][1]), "=r"(a[mi][2]), "=r"(a[mi][3])
                : "r"(addr));
        }
        int l16 = lane & 15;
        #pragma unroll
        for (int ni = 0; ni < 4; ++ni) {
            uint32_t addr = bBase + (uint32_t)(warp_n * 32 + ni * 8 + (l16 & 7)) * ROWB
                          + ks * 32 + ((l16 >> 3) << 4);
            asm volatile("ldmatrix.sync.aligned.m8n8.x2.shared.b16 {%0,%1}, [%2];"
                : "=r"(b[ni][0]), "=r"(b[ni][1])
                : "r"(addr));
        }
        #pragma unroll
        for (int mi = 0; mi < 4; ++mi)
            #pragma unroll
            for (int ni = 0; ni < 4; ++ni)
                asm volatile("mma.sync.aligned.m16n8k16.row.col.f32.f16.f16.f32 "
                    "{%0,%1,%2,%3}, {%4,%5,%6,%7}, {%8,%9}, {%0,%1,%2,%3};"
                    : "+f"(acc[mi][ni][0]), "+f"(acc[mi][ni][1]),
                      "+f"(acc[mi][ni][2]), "+f"(acc[mi][ni][3])
                    : "r"(a[mi][0]), "r"(a[mi][1]), "r"(a[mi][2]), "r"(a[mi][3]),
                      "r"(b[ni][0]), "r"(b[ni][1]));
    }
}

__global__ void __launch_bounds__(256, 2) gemm_kernel() {
    extern __shared__ char smem[];
    const uint32_t sb = smem_u32(smem);
    const int tid = threadIdx.x, wid = tid >> 5, lane = tid & 31;
    const int warp_m = wid & 1;      // 2 warp rows of 64
    const int warp_n = wid >> 1;     // 4 warp cols of 32

    // L2-friendly supertile mapping: groups of 8 M-tiles per N sweep
    const int NTM = BROWS / BM;      // 32
    const int NTN = NTOT / BN;       // 64
    const int GM = 8;
    int bid = blockIdx.x;
    int g = bid / (GM * NTN), r = bid % (GM * NTN);
    int mt = g * GM + (r % GM);
    int nt = r / GM;
    int m0 = mt * BM, n0 = nt * BN;
    (void)NTM;

    float acc[4][4][4];
    #pragma unroll
    for (int mi = 0; mi < 4; ++mi)
        #pragma unroll
        for (int ni = 0; ni < 4; ++ni)
            #pragma unroll
            for (int q = 0; q < 4; ++q) acc[mi][ni][q] = 0.f;

    // prologue: stages 0 and 1
    load_stage(sb, tid, m0, n0, 0, 0); CP_COMMIT();
    load_stage(sb, tid, m0, n0, 1, 1); CP_COMMIT();

    for (int i = 0; i < NITER; ++i) {
        if (i + 2 < NITER) {
            CP_WAIT(1);
            __syncthreads();
            load_stage(sb, tid, m0, n0, i + 2, (i + 2) % STAGES);
            CP_COMMIT();
        } else if (i + 2 == NITER) {
            CP_WAIT(1);
            __syncthreads();
        } else {
            CP_WAIT(0);
            __syncthreads();
        }
        int buf = i % STAGES;
        compute_stage(sb + buf * ATILE, sb + SM_BOFF + buf * BTILE,
                      warp_m, warp_n, lane, acc);
    }

    // write fp32 gates to scratch
    #pragma unroll
    for (int mi = 0; mi < 4; ++mi) {
        #pragma unroll
        for (int ni = 0; ni < 4; ++ni) {
            int r0 = m0 + warp_m * 64 + mi * 16 + (lane >> 2);
            int cb = n0 + warp_n * 32 + ni * 8 + (lane & 3) * 2;
            float2 v0 = make_float2(acc[mi][ni][0], acc[mi][ni][1]);
            float2 v1 = make_float2(acc[mi][ni][2], acc[mi][ni][3]);
            *reinterpret_cast<float2*>(&g_G[(size_t)r0 * NTOT + cb]) = v0;
            *reinterpret_cast<float2*>(&g_G[(size_t)(r0 + 8) * NTOT + cb]) = v1;
        }
    }
}

// ============================================================
// K4: elementwise LSTM epilogue
// ============================================================
__global__ void epilogue_kernel(const float* __restrict__ cin,
                                const float* __restrict__ bfv, const float* __restrict__ biv,
                                const float* __restrict__ bcv, const float* __restrict__ bov,
                                float* __restrict__ out) {
    int i = blockIdx.x * blockDim.x + threadIdx.x;   // over 4096*2048
    int row = i >> 11;
    int u   = i & 2047;
    size_t base = (size_t)row * NTOT;
    float f = g_G[base + u]            + bfv[u];
    float g = g_G[base + UNITS + u]    + biv[u];     // i gate
    float c = g_G[base + 2 * UNITS + u] + bcv[u];    // candidate
    float o = g_G[base + 3 * UNITS + u] + bov[u];

    float ft = sigf(f);
    float it = sigf(g);
    float gt = tanhfast(c);
    float ot = sigf(o);
    float nc = ft * cin[i] + it * gt;
    float nh = ot * tanhfast(nc);
    out[i] = nh;                                      // new_h
    out[(size_t)BROWS * UNITS + i] = nc;              // new_c
}

// ============================================================
// kernel_launch
// ============================================================
extern "C" void kernel_launch(void* const* d_in, const int* in_sizes, int n_in,
                              void* d_out, int out_size) {
    const float* x  = (const float*)d_in[0];
    const float* h  = (const float*)d_in[1];
    const float* c  = (const float*)d_in[2];
    const float* Wf = (const float*)d_in[3];
    const float* bf = (const float*)d_in[4];
    const float* Wi = (const float*)d_in[5];
    const float* bi = (const float*)d_in[6];
    const float* Wc = (const float*)d_in[7];
    const float* bc = (const float*)d_in[8];
    const float* Wo = (const float*)d_in[9];
    const float* bo = (const float*)d_in[10];
    float* out = (float*)d_out;

    // K1: pack z -> fp16
    pack_z_kernel<<<(BROWS * KTOT) / 1024, 1024>>>(x, h);

    // K2: transpose + convert weights
    dim3 tg(KTOT / 64, UNITS / 32, 4);
    transpose_w_kernel<<<tg, dim3(32, 8)>>>(Wf, Wi, Wc, Wo);

    // K3: GEMM
    static bool attr_set = false;
    if (!attr_set) {
        cudaFuncSetAttribute(gemm_kernel,
                             cudaFuncAttributeMaxDynamicSharedMemorySize, SMEM_TOTAL);
        attr_set = true;
    }
    int grid = (BROWS / BM) * (NTOT / BN);   // 2048
    gemm_kernel<<<grid, 256, SMEM_TOTAL>>>();

    // K4: epilogue
    epilogue_kernel<<<(BROWS * UNITS) / 256, 256>>>(c, bf, bi, bc, bo, out);
}